// round 9
// baseline (speedup 1.0000x reference)
#include <cuda_runtime.h>
#include <cuda_bf16.h>
#include <cstdint>
#include <math.h>

// S4D as 1024 batched small GEMMs on mma.sync (HMMA, sm_80 baseline).
//
// K[h, 32k+j] = Re( sum_n cc_n * (r_n^32)^k * r_n^j ),  r_n = exp(dtA[h,n]).
// Per head:  D[128x32] = A[128 x 128] * B[32 x 128]^T   (bf16, fp32 accum)
//   A[k, 2n+0/1] = (Vr_hi, Vi_hi),  A[k, 64+2n+0/1] = (Vr_lo, Vi_lo),  V = r^(32k)
//   B[j, 2n+0/1] = (Ur_hi, -Ui_hi), B[j, 64+2n+0/1] = (Ur_lo, -Ui_lo), U = cc*r^j
// D = Ahi*Bhi + Ahi*Blo + Alo*Bhi (lo*lo dropped ~2^-18): 12 k16 MMA steps.
// R9: march phase cheapened — split via cvt.rn.bf16x2 + PRMT residuals
// (6 insts/value vs ~12), dual independent march chains (R^2 stepping) to
// halve serial FFMA latency, strength-reduced STS addressing.

#define AST 136   // A row stride in halves (272B; LDSM conflict-free)
#define BST 136

__device__ __forceinline__ float2 cmul(float2 a, float2 b) {
    return make_float2(fmaf(a.x, b.x, -a.y * b.y), fmaf(a.x, b.y, a.y * b.x));
}
// hi = {bf16rn(x) lo-half, bf16rn(y) hi-half}; lo = packed exact residuals
__device__ __forceinline__ void split_pack(float x, float y, uint32_t& hi, uint32_t& lo) {
    asm("cvt.rn.bf16x2.f32 %0, %1, %2;" : "=r"(hi) : "f"(y), "f"(x));
    uint32_t xh, yh;
    asm("prmt.b32 %0, %1, %2, 0x1054;" : "=r"(xh) : "r"(hi), "r"(0));
    asm("prmt.b32 %0, %1, %2, 0x3254;" : "=r"(yh) : "r"(hi), "r"(0));
    float xr = x - __uint_as_float(xh);
    float yr = y - __uint_as_float(yh);
    asm("cvt.rn.bf16x2.f32 %0, %1, %2;" : "=r"(lo) : "f"(yr), "f"(xr));
}
__device__ __forceinline__ uint32_t smem_u32(const void* p) {
    uint32_t a;
    asm("{ .reg .u64 t; cvta.to.shared.u64 t, %1; cvt.u32.u64 %0, t; }" : "=r"(a) : "l"(p));
    return a;
}
__device__ __forceinline__ void sts32(uint32_t addr, uint32_t v) {
    asm volatile("st.shared.b32 [%0], %1;" :: "r"(addr), "r"(v) : "memory");
}
__device__ __forceinline__ void ldsm4(uint32_t& r0, uint32_t& r1, uint32_t& r2,
                                      uint32_t& r3, uint32_t addr) {
    asm volatile("ldmatrix.sync.aligned.m8n8.x4.shared.b16 {%0,%1,%2,%3}, [%4];"
                 : "=r"(r0), "=r"(r1), "=r"(r2), "=r"(r3) : "r"(addr));
}
__device__ __forceinline__ void mma16816(float* c, uint32_t a0, uint32_t a1,
                                         uint32_t a2, uint32_t a3,
                                         uint32_t b0, uint32_t b1) {
    asm("mma.sync.aligned.m16n8k16.row.col.f32.bf16.bf16.f32 "
        "{%0,%1,%2,%3}, {%4,%5,%6,%7}, {%8,%9}, {%0,%1,%2,%3};"
        : "+f"(c[0]), "+f"(c[1]), "+f"(c[2]), "+f"(c[3])
        : "r"(a0), "r"(a1), "r"(a2), "r"(a3), "r"(b0), "r"(b1));
}

__global__ void __launch_bounds__(128, 5)
s4d_mma(float* __restrict__ out,
        const float* __restrict__ C, const float* __restrict__ log_dt,
        const float* __restrict__ lAr, const float* __restrict__ Ai) {
    __shared__ __align__(16) __nv_bfloat16 sA[128 * AST];  // 34816 B
    __shared__ __align__(16) __nv_bfloat16 sB[32 * BST];   //  8704 B
    __shared__ float2 sR[32], sCC[32];

    const int h    = blockIdx.x;
    const int tid  = threadIdx.x;
    const int wid  = tid >> 5;
    const int lane = tid & 31;

    // ---- warp 0: per-mode constants (the only transcendentals) ----
    if (wid == 0) {
        const int n = lane, idx = h * 32 + n;
        float dt = expf(log_dt[h]);
        float ar = -expf(lAr[idx]);
        float ai = Ai[idx];
        float x  = ar * dt, th = ai * dt;
        float sy, cy; sincosf(th, &sy, &cy);
        float ex = expf(x);
        float2 r = make_float2(ex * cy, ex * sy);
        float den  = ar * ar + ai * ai;
        float c2   = 2.0f * C[idx] / den;
        float wre  = r.x - 1.0f, wim = r.y;
        sR[n]  = r;
        sCC[n] = make_float2(c2 * (wre * ar + wim * ai),
                             c2 * (wim * ar - wre * ai));
    }
    __syncthreads();

    // ---- all threads: march table chunks (mode n, chunk c) ----
    {
        const int n = tid & 31, c = tid >> 5;
        float2 r  = sR[n], cc = sCC[n];
        float2 r2  = cmul(r, r),   r4  = cmul(r2, r2);
        float2 r8  = cmul(r4, r4), r16 = cmul(r8, r8);
        float2 R   = cmul(r16, r16);                 // r^32

        // B: U[j] = cc * r^j, rows j in [8c, 8c+8), dual chains step r^2
        {
            float2 u0 = cc;
            if (c & 1) u0 = cmul(u0, r8);
            if (c & 2) u0 = cmul(u0, r16);
            float2 u1 = cmul(u0, r);
            uint32_t w = smem_u32(sB) + (8 * c) * (BST * 2) + 4 * n;
            #pragma unroll
            for (int it = 0; it < 4; ++it) {
                uint32_t hi, lo;
                split_pack(u0.x, -u0.y, hi, lo);
                sts32(w, hi); sts32(w + 128, lo);
                split_pack(u1.x, -u1.y, hi, lo);
                sts32(w + BST * 2, hi); sts32(w + BST * 2 + 128, lo);
                u0 = cmul(u0, r2); u1 = cmul(u1, r2);
                w += 2 * BST * 2;
            }
        }

        // A: V[k] = R^k, rows k in [32c, 32c+32), dual chains step R^2
        {
            float2 R2  = cmul(R, R),   R4  = cmul(R2, R2);
            float2 R8  = cmul(R4, R4), R16 = cmul(R8, R8);
            float2 R32 = cmul(R16, R16), R64 = cmul(R32, R32);
            float2 v0 = make_float2(1.0f, 0.0f);
            if (c & 1) v0 = R32;
            if (c & 2) v0 = cmul(v0, R64);
            float2 v1 = cmul(v0, R);
            uint32_t w = smem_u32(sA) + (32 * c) * (AST * 2) + 4 * n;
            #pragma unroll
            for (int it = 0; it < 16; ++it) {
                uint32_t hi, lo;
                split_pack(v0.x, v0.y, hi, lo);
                sts32(w, hi); sts32(w + 128, lo);
                split_pack(v1.x, v1.y, hi, lo);
                sts32(w + AST * 2, hi); sts32(w + AST * 2 + 128, lo);
                v0 = cmul(v0, R2); v1 = cmul(v1, R2);
                w += 2 * AST * 2;
            }
        }
    }
    __syncthreads();

    // ---- per-lane ldmatrix base addresses ----
    const uint32_t sA_a = smem_u32(sA), sB_a = smem_u32(sB);
    uint32_t aAddr[2], bAddr[2];
    {
        int arow = 32 * wid + (lane & 15);
        uint32_t achk = (lane >> 4) * 16;
        aAddr[0] = sA_a + arow * (AST * 2) + achk;
        aAddr[1] = aAddr[0] + 16 * (AST * 2);
        int brow = 8 * (lane >> 4) + (lane & 7);
        uint32_t bchk = ((lane >> 3) & 1) * 16;
        bAddr[0] = sB_a + brow * (BST * 2) + bchk;
        bAddr[1] = bAddr[0] + 16 * (BST * 2);
    }

    // ---- mma: warp wid computes D rows [32*wid, 32*wid+32) ----
    float acc[2][4][4];
    #pragma unroll
    for (int mt = 0; mt < 2; ++mt)
        #pragma unroll
        for (int nt = 0; nt < 4; ++nt)
            #pragma unroll
            for (int e = 0; e < 4; ++e) acc[mt][nt][e] = 0.0f;

    #pragma unroll
    for (int t = 0; t < 3; ++t) {
        const uint32_t ka = (t == 2) ? 128u : 0u;   // byte offset of A lo half
        const uint32_t kb = (t == 1) ? 128u : 0u;   // byte offset of B lo half
        #pragma unroll
        for (int q = 0; q < 4; ++q) {
            const uint32_t qa = ka + 32u * q, qb = kb + 32u * q;
            uint32_t a[2][4], b[2][4];
            ldsm4(a[0][0], a[0][1], a[0][2], a[0][3], aAddr[0] + qa);
            ldsm4(a[1][0], a[1][1], a[1][2], a[1][3], aAddr[1] + qa);
            ldsm4(b[0][0], b[0][1], b[0][2], b[0][3], bAddr[0] + qb);
            ldsm4(b[1][0], b[1][1], b[1][2], b[1][3], bAddr[1] + qb);
            #pragma unroll
            for (int mt = 0; mt < 2; ++mt)
                #pragma unroll
                for (int nt = 0; nt < 4; ++nt)
                    mma16816(acc[mt][nt], a[mt][0], a[mt][1], a[mt][2], a[mt][3],
                             b[nt >> 1][(nt & 1) * 2], b[nt >> 1][(nt & 1) * 2 + 1]);
        }
    }

    // ---- store D from fragments: out[h*4096 + row*32 + col] ----
    const int g  = lane >> 2;
    const int tg = lane & 3;
    float* const ob = out + (size_t)h * 4096;
    #pragma unroll
    for (int mt = 0; mt < 2; ++mt) {
        const int row = 32 * wid + 16 * mt + g;
        #pragma unroll
        for (int nt = 0; nt < 4; ++nt) {
            float* p = ob + row * 32 + 8 * nt + 2 * tg;
            *(float2*)p            = make_float2(acc[mt][nt][0], acc[mt][nt][1]);
            *(float2*)(p + 8 * 32) = make_float2(acc[mt][nt][2], acc[mt][nt][3]);
        }
    }
}

// ---------------- launch ----------------------------------------------------
extern "C" void kernel_launch(void* const* d_in, const int* in_sizes, int n_in,
                              void* d_out, int out_size) {
    const float* C      = (const float*)d_in[0];
    const float* log_dt = (const float*)d_in[1];
    const float* lAr    = (const float*)d_in[2];
    const float* Ai     = (const float*)d_in[3];
    const int H = in_sizes[1];               // 1024

    s4d_mma<<<H, 128>>>((float*)d_out, C, log_dt, lAr, Ai);
}